// round 4
// baseline (speedup 1.0000x reference)
#include <cuda_runtime.h>
#include <math.h>

#define BB 32
#define NREG 196
#define EE 512
#define HH 512
#define SEQ 64
#define VV 32000

#define NBLK 148
#define NTHR 256

// ---------------- scratch (device globals; no allocations) ----------------
__device__ float g_fmean[BB * EE];
__device__ float g_h[2][BB * HH];       // [b][k] (attention dots)
__device__ float g_hT[2][HH * BB];      // [k][b] (gate GEMVs)
__device__ float g_cT[HH * BB];
__device__ float g_sc[BB * NREG];
__device__ float g_actT[(EE + HH) * BB];// [k][b]: k<512 ctx, k>=512 emb*sqrtE
__device__ float g_xT[EE * BB];
__device__ float g_Hall[SEQ * BB * HH]; // row (t*32+b)
__device__ unsigned g_bar_count;        // invariant: 0 outside barriers
__device__ unsigned g_bar_gen;          // monotonic across replays (ok)

// ---------------- grid-wide barrier ----------------
__device__ __forceinline__ void gridbar() {
    __syncthreads();
    if (threadIdx.x == 0) {
        unsigned gen = *((volatile unsigned*)&g_bar_gen);
        __threadfence();
        if (atomicAdd(&g_bar_count, 1u) == (unsigned)(gridDim.x - 1)) {
            g_bar_count = 0;
            __threadfence();
            atomicAdd(&g_bar_gen, 1u);
        } else {
            while (*((volatile unsigned*)&g_bar_gen) == gen) { __nanosleep(64); }
        }
        __threadfence();
    }
    __syncthreads();
}

__device__ __forceinline__ float warpsum(float v) {
#pragma unroll
    for (int o = 16; o; o >>= 1) v += __shfl_xor_sync(0xffffffffu, v, o);
    return v;
}

__device__ __forceinline__ float warpdot512(const float* __restrict__ a,
                                            const float* __restrict__ b, int lane) {
    float s = 0.f;
#pragma unroll
    for (int c = 0; c < 4; c++) {
        float4 av = *(const float4*)(a + c * 128 + lane * 4);
        float4 bv = *(const float4*)(b + c * 128 + lane * 4);
        s += av.x * bv.x + av.y * bv.y + av.z * bv.z + av.w * bv.w;
    }
    return s;
}

// dot of a 512-float weight row with transposed activations actT[k][b], b=lane
__device__ __forceinline__ float rowdotT512(const float* __restrict__ wrow,
                                            const float* __restrict__ actT, int lane) {
    float acc = 0.f;
#pragma unroll 4
    for (int kg = 0; kg < 128; kg++) {
        float4 wv = *(const float4*)(wrow + kg * 4);
        const float* ap = actT + (kg * 4) * BB + lane;
        acc += wv.x * ap[0 * BB];
        acc += wv.y * ap[1 * BB];
        acc += wv.z * ap[2 * BB];
        acc += wv.w * ap[3 * BB];
    }
    return acc;
}

// ---------------- persistent recurrence kernel ----------------
__global__ void __launch_bounds__(NTHR) recurrence_kernel(
    const float* __restrict__ features, const int* __restrict__ captions,
    const float* __restrict__ embed_W,
    const float* __restrict__ ihW, const float* __restrict__ ihb,
    const float* __restrict__ icW, const float* __restrict__ icb,
    const float* __restrict__ rW,  const float* __restrict__ rb,
    const float* __restrict__ Wih, const float* __restrict__ Whh,
    const float* __restrict__ bih, const float* __restrict__ bhh)
{
    const int tid  = threadIdx.x;
    const int lane = tid & 31;
    const int w    = tid >> 5;
    const int gtid = blockIdx.x * NTHR + tid;
    const int wid_g  = gtid >> 5;
    const int nwarps = (NBLK * NTHR) >> 5;
    const int gstride = NBLK * NTHR;

    __shared__ float sh_attn[NREG];
    __shared__ float sh_red[NTHR / 32];
    __shared__ float sh_x[4][2][BB];     // P3 partials [eo_slot][khalf][b]
    __shared__ float sh_g[2][4][BB];     // P4 partials [hi_slot][gate][b]

    // ---- init a: fmean
    for (int idx = gtid; idx < BB * EE; idx += gstride) {
        int b = idx >> 9, e = idx & 511;
        const float* fp = features + (size_t)b * NREG * EE + e;
        float s = 0.f;
        for (int n = 0; n < NREG; n++) s += fp[n * EE];
        g_fmean[idx] = s * (1.0f / NREG);
    }
    gridbar();

    // ---- init b: h0 / c0
    for (int task = wid_g; task < 2 * BB * HH; task += nwarps) {
        int which = task & 1;
        int m = task >> 1;
        int b = m >> 9, eo = m & 511;
        const float* Wrow = (which ? icW : ihW) + (size_t)eo * EE;
        float s = warpsum(warpdot512(Wrow, g_fmean + b * EE, lane));
        if (lane == 0) {
            if (which) {
                g_cT[eo * BB + b] = s + icb[eo];
            } else {
                float hv = s + ihb[eo];
                g_h[0][m] = hv;
                g_hT[0][eo * BB + b] = hv;
            }
        }
    }
    gridbar();

    for (int t = 0; t < SEQ; t++) {
        const float* h_cur  = g_h[t & 1];
        const float* hT_cur = g_hT[t & 1];
        float*       h_nxt  = g_h[(t & 1) ^ 1];
        float*       hT_nxt = g_hT[(t & 1) ^ 1];

        // ---- P1: attention scores (warp per (b,n)) + embT fill
        for (int task = wid_g; task < BB * NREG; task += nwarps) {
            int b = task / NREG, n = task - b * NREG;
            float s = warpsum(warpdot512(features + ((size_t)b * NREG + n) * EE,
                                         h_cur + b * EE, lane));
            if (lane == 0) g_sc[task] = s;
        }
        for (int idx = gtid; idx < BB * EE; idx += gstride) {
            int b = idx >> 9, k = idx & 511;
            int tok = captions[b * SEQ + t];
            g_actT[(EE + k) * BB + b] =
                embed_W[(size_t)tok * EE + k] * 22.62741699796952f; // sqrt(512)
        }
        gridbar();

        // ---- P2: softmax (redundant per 4-block group) + context chunk
        if (blockIdx.x < BB * 4) {
            int b = blockIdx.x >> 2;
            int chunk = blockIdx.x & 3;

            float v = (tid < NREG) ? g_sc[b * NREG + tid] : -1e30f;
            float m = v;
#pragma unroll
            for (int o = 16; o; o >>= 1) m = fmaxf(m, __shfl_xor_sync(0xffffffffu, m, o));
            if (lane == 0) sh_red[w] = m;
            __syncthreads();
            float mx = sh_red[0];
#pragma unroll
            for (int i = 1; i < NTHR / 32; i++) mx = fmaxf(mx, sh_red[i]);

            float ev = (tid < NREG) ? __expf(v - mx) : 0.f;
            float ps = warpsum(ev);
            __syncthreads();
            if (lane == 0) sh_red[w] = ps;
            __syncthreads();
            float tot = 0.f;
#pragma unroll
            for (int i = 0; i < NTHR / 32; i++) tot += sh_red[i];
            if (tid < NREG) sh_attn[tid] = ev / tot;
            __syncthreads();

            if (tid < 128) {
                int e = chunk * 128 + tid;
                const float* fp = features + (size_t)b * NREG * EE + e;
                float s = 0.f;
#pragma unroll 4
                for (int n = 0; n < NREG; n++) s += sh_attn[n] * fp[n * EE];
                g_actT[e * BB + b] = s;
            }
        }
        gridbar();

        // ---- P3: x = [ctx; emb] @ rW^T + rb
        // 4 eo per block-iter, 2 warps per eo (k halves), combine in smem.
        for (int e0 = blockIdx.x * 4; e0 < EE; e0 += NBLK * 4) {
            int slot = w >> 1;          // 0..3
            int kh   = w & 1;           // k half
            int eo   = e0 + slot;
            const float* wr = rW + (size_t)eo * (EE + HH) + kh * 512;
            float acc = rowdotT512(wr, g_actT + (size_t)kh * 512 * BB, lane);
            sh_x[slot][kh][lane] = acc;
            __syncthreads();
            if (w < 4) {
                int eo2 = e0 + w;
                g_xT[eo2 * BB + lane] = sh_x[w][0][lane] + sh_x[w][1][lane] + rb[eo2];
            }
            __syncthreads();
        }
        gridbar();

        // ---- P4: gates + cell. 2 hi per block-iter, 4 warps per hi (one gate each),
        // block-local combine does the LSTM cell update.
        for (int h0 = blockIdx.x * 2; h0 < HH; h0 += NBLK * 2) {
            int slot = w >> 2;          // 0/1
            int g    = w & 3;           // gate
            int hi   = h0 + slot;
            int j    = g * HH + hi;
            float acc = rowdotT512(Wih + (size_t)j * EE, g_xT, lane)
                      + rowdotT512(Whh + (size_t)j * HH, hT_cur, lane);
            sh_g[slot][g][lane] = acc;
            __syncthreads();
            if (w < 2) {
                int hh = h0 + w;
                float iv = sh_g[w][0][lane] + bih[hh]          + bhh[hh];
                float fv = sh_g[w][1][lane] + bih[HH + hh]     + bhh[HH + hh];
                float gv = sh_g[w][2][lane] + bih[2 * HH + hh] + bhh[2 * HH + hh];
                float ov = sh_g[w][3][lane] + bih[3 * HH + hh] + bhh[3 * HH + hh];
                float si = 1.f / (1.f + __expf(-iv));
                float sf = 1.f / (1.f + __expf(-fv));
                float so = 1.f / (1.f + __expf(-ov));
                float c2 = sf * g_cT[hh * BB + lane] + si * tanhf(gv);
                float h2 = so * tanhf(c2);
                g_cT[hh * BB + lane] = c2;
                hT_nxt[hh * BB + lane] = h2;
                h_nxt[lane * HH + hh] = h2;
                g_Hall[((size_t)t * BB + lane) * HH + hh] = h2;
            }
            __syncthreads();
        }
        gridbar();
    }
}

// ---------------- output GEMM (f32x2 packed): out[2048,32000] ----------------
#define BM 128
#define BN 128
#define BK 16
#define TM 8
#define TN 8

__device__ __forceinline__ void ffma2(unsigned long long& d,
                                      unsigned long long a, unsigned long long b) {
    asm volatile("fma.rn.f32x2 %0, %1, %2, %0;" : "+l"(d) : "l"(a), "l"(b));
}
__device__ __forceinline__ unsigned long long dup2(float x) {
    unsigned long long r;
    asm("mov.b64 %0, {%1, %1};" : "=l"(r) : "f"(x));
    return r;
}
__device__ __forceinline__ void unpack2(unsigned long long v, float& lo, float& hi) {
    asm("mov.b64 {%0, %1}, %2;" : "=f"(lo), "=f"(hi) : "l"(v));
}

__global__ void __launch_bounds__(256) out_gemm(
    const float* __restrict__ outW, const float* __restrict__ outb,
    float* __restrict__ out)
{
    __shared__ __align__(16) unsigned long long As2[BK][BM]; // (a,a) duplicated, 16KB
    __shared__ __align__(16) float Bs[BK][BN];               // 8KB

    const int bn = blockIdx.x;
    const int bm = blockIdx.y;
    const int tid = threadIdx.x;
    const int tx = tid & 15;
    const int ty = tid >> 4;

    unsigned long long acc2[TM][TN / 2];
#pragma unroll
    for (int i = 0; i < TM; i++)
#pragma unroll
        for (int j = 0; j < TN / 2; j++) acc2[i][j] = 0ull;

    const float* Abase = g_Hall + (size_t)bm * BM * 512;
    const float* Bbase = outW   + (size_t)bn * BN * 512;

    for (int k0 = 0; k0 < 512; k0 += BK) {
#pragma unroll
        for (int i = 0; i < 2; i++) {
            int f = tid + i * 256;
            int row = f >> 2;
            int cg  = (f & 3) * 4;
            float4 va = *(const float4*)(Abase + (size_t)row * 512 + k0 + cg);
            As2[cg + 0][row] = dup2(va.x); As2[cg + 1][row] = dup2(va.y);
            As2[cg + 2][row] = dup2(va.z); As2[cg + 3][row] = dup2(va.w);
            float4 vb = *(const float4*)(Bbase + (size_t)row * 512 + k0 + cg);
            Bs[cg + 0][row] = vb.x; Bs[cg + 1][row] = vb.y;
            Bs[cg + 2][row] = vb.z; Bs[cg + 3][row] = vb.w;
        }
        __syncthreads();
#pragma unroll
        for (int k = 0; k < BK; k++) {
            unsigned long long ap[TM], bp[TN / 2];
#pragma unroll
            for (int i = 0; i < TM; i += 2) {
                ulonglong2 v = *(const ulonglong2*)&As2[k][ty * TM + i];
                ap[i] = v.x; ap[i + 1] = v.y;
            }
#pragma unroll
            for (int j = 0; j < TN / 2; j += 2) {
                ulonglong2 v = *(const ulonglong2*)&Bs[k][tx * TN + j * 2];
                bp[j] = v.x; bp[j + 1] = v.y;
            }
#pragma unroll
            for (int i = 0; i < TM; i++)
#pragma unroll
                for (int j = 0; j < TN / 2; j++) ffma2(acc2[i][j], ap[i], bp[j]);
        }
        __syncthreads();
    }

#pragma unroll
    for (int i = 0; i < TM; i++) {
        int m = bm * BM + ty * TM + i;
        int tt = m >> 5, b = m & 31;
        float* orow = out + ((size_t)b * SEQ + tt) * VV + bn * BN + tx * TN;
        const float* brow = outb + bn * BN + tx * TN;
#pragma unroll
        for (int j = 0; j < TN; j += 4) {
            float4 bias = *(const float4*)(brow + j);
            float p0, p1, p2, p3;
            unpack2(acc2[i][j / 2],     p0, p1);
            unpack2(acc2[i][j / 2 + 1], p2, p3);
            float4 v;
            v.x = p0 + bias.x; v.y = p1 + bias.y;
            v.z = p2 + bias.z; v.w = p3 + bias.w;
            *(float4*)(orow + j) = v;
        }
    }
}

extern "C" void kernel_launch(void* const* d_in, const int* in_sizes, int n_in,
                              void* d_out, int out_size)
{
    const float* features = (const float*)d_in[0];
    const int*   captions = (const int*)d_in[1];
    const float* embed_W  = (const float*)d_in[2];
    const float* ihW = (const float*)d_in[3];
    const float* ihb = (const float*)d_in[4];
    const float* icW = (const float*)d_in[5];
    const float* icb = (const float*)d_in[6];
    const float* rW  = (const float*)d_in[7];
    const float* rb  = (const float*)d_in[8];
    const float* Wih = (const float*)d_in[9];
    const float* Whh = (const float*)d_in[10];
    const float* bih = (const float*)d_in[11];
    const float* bhh = (const float*)d_in[12];
    const float* outW = (const float*)d_in[13];
    const float* outb = (const float*)d_in[14];

    recurrence_kernel<<<NBLK, NTHR>>>(features, captions, embed_W,
                                      ihW, ihb, icW, icb, rW, rb,
                                      Wih, Whh, bih, bhh);
    dim3 grid(VV / BN, (SEQ * BB) / BM);
    out_gemm<<<grid, 256>>>(outW, outb, (float*)d_out);
}

// round 6
// speedup vs baseline: 1.6152x; 1.6152x over previous
#include <cuda_runtime.h>
#include <cuda_bf16.h>
#include <math.h>
#include <stdint.h>

#define BB 32
#define NREG 196
#define EE 512
#define HH 512
#define SEQ 64
#define VV 32000

#define NBLK 148
#define NTHR 256

// ---------------- scratch (device globals; no allocations) ----------------
__device__ float g_fmean[BB * EE];
__device__ float g_hbuf[2][BB * HH];
__device__ float g_c[BB * HH];
__device__ float g_ctx[BB * EE];
__device__ float g_x[BB * EE];
__device__ __align__(16) float g_Hall[SEQ * BB * HH];   // row (t*32+b)
__device__ unsigned g_bar_count;
__device__ unsigned g_bar_gen;

// bf16 split buffers for tensor-core GEMM
__device__ __align__(16) __nv_bfloat16 g_AH[SEQ * BB * HH];
__device__ __align__(16) __nv_bfloat16 g_AL[SEQ * BB * HH];
__device__ __align__(16) __nv_bfloat16 g_WH[(size_t)VV * EE];
__device__ __align__(16) __nv_bfloat16 g_WL[(size_t)VV * EE];

// ---------------- grid-wide barrier ----------------
__device__ __forceinline__ void gridbar() {
    __syncthreads();
    if (threadIdx.x == 0) {
        unsigned gen = *((volatile unsigned*)&g_bar_gen);
        __threadfence();
        if (atomicAdd(&g_bar_count, 1u) == (unsigned)(gridDim.x - 1)) {
            g_bar_count = 0;
            __threadfence();
            atomicAdd(&g_bar_gen, 1u);
        } else {
            while (*((volatile unsigned*)&g_bar_gen) == gen) { __nanosleep(64); }
        }
        __threadfence();
    }
    __syncthreads();
}

__device__ __forceinline__ float warpsum(float v) {
#pragma unroll
    for (int o = 16; o; o >>= 1) v += __shfl_xor_sync(0xffffffffu, v, o);
    return v;
}

__device__ __forceinline__ float warpdot512(const float* __restrict__ a,
                                            const float* __restrict__ b, int lane) {
    float s = 0.f;
#pragma unroll
    for (int c = 0; c < 4; c++) {
        float4 av = *(const float4*)(a + c * 128 + lane * 4);
        float4 bv = *(const float4*)(b + c * 128 + lane * 4);
        s += av.x * bv.x + av.y * bv.y + av.z * bv.z + av.w * bv.w;
    }
    return s;
}

// ---------------- persistent recurrence kernel (R2 version — known good) ----
__global__ void __launch_bounds__(NTHR) recurrence_kernel(
    const float* __restrict__ features, const int* __restrict__ captions,
    const float* __restrict__ embed_W,
    const float* __restrict__ ihW, const float* __restrict__ ihb,
    const float* __restrict__ icW, const float* __restrict__ icb,
    const float* __restrict__ rW,  const float* __restrict__ rb,
    const float* __restrict__ Wih, const float* __restrict__ Whh,
    const float* __restrict__ bih, const float* __restrict__ bhh)
{
    const int tid  = threadIdx.x;
    const int lane = tid & 31;
    const int gtid = blockIdx.x * NTHR + tid;
    const int wid_g  = gtid >> 5;
    const int nwarps = (gridDim.x * NTHR) >> 5;
    const int gstride = gridDim.x * NTHR;

    __shared__ __align__(16) float sh_h[HH];
    __shared__ float sh_sc[NREG];
    __shared__ float sh_red[NTHR / 32];

    for (int idx = gtid; idx < BB * EE; idx += gstride) {
        int b = idx >> 9, e = idx & 511;
        const float* fp = features + (size_t)b * NREG * EE + e;
        float s = 0.f;
        for (int n = 0; n < NREG; n++) s += fp[n * EE];
        g_fmean[idx] = s * (1.0f / NREG);
    }
    gridbar();

    for (int task = wid_g; task < 2 * BB * HH; task += nwarps) {
        int which = task & 1;
        int m = task >> 1;
        int b = m >> 9, eo = m & 511;
        const float* Wrow = (which ? icW : ihW) + (size_t)eo * EE;
        float s = warpsum(warpdot512(Wrow, g_fmean + b * EE, lane));
        if (lane == 0) {
            if (which) g_c[m] = s + icb[eo];
            else       g_hbuf[0][m] = s + ihb[eo];
        }
    }
    gridbar();

    for (int t = 0; t < SEQ; t++) {
        const float* hcur = g_hbuf[t & 1];
        float*       hnxt = g_hbuf[(t & 1) ^ 1];

        if (blockIdx.x < BB) {
            int b = blockIdx.x;
            for (int e = tid; e < HH; e += NTHR) sh_h[e] = hcur[b * HH + e];
            __syncthreads();
            int w = tid >> 5;
            for (int n = w; n < NREG; n += NTHR / 32) {
                float s = warpsum(warpdot512(features + ((size_t)b * NREG + n) * EE, sh_h, lane));
                if (lane == 0) sh_sc[n] = s;
            }
            __syncthreads();
            float mx = -1e30f;
            for (int n = tid; n < NREG; n += NTHR) mx = fmaxf(mx, sh_sc[n]);
#pragma unroll
            for (int o = 16; o; o >>= 1) mx = fmaxf(mx, __shfl_xor_sync(0xffffffffu, mx, o));
            if (lane == 0) sh_red[w] = mx;
            __syncthreads();
            mx = sh_red[0];
#pragma unroll
            for (int i = 1; i < NTHR / 32; i++) mx = fmaxf(mx, sh_red[i]);
            __syncthreads();
            float ssum = 0.f;
            for (int n = tid; n < NREG; n += NTHR) {
                float ev = __expf(sh_sc[n] - mx);
                sh_sc[n] = ev;
                ssum += ev;
            }
            ssum = warpsum(ssum);
            if (lane == 0) sh_red[w] = ssum;
            __syncthreads();
            float tot = 0.f;
#pragma unroll
            for (int i = 0; i < NTHR / 32; i++) tot += sh_red[i];
            float inv = 1.0f / tot;
            __syncthreads();
            for (int n = tid; n < NREG; n += NTHR) sh_sc[n] *= inv;
            __syncthreads();
            for (int e = tid; e < EE; e += NTHR) {
                const float* fp = features + (size_t)b * NREG * EE + e;
                float s = 0.f;
                for (int n = 0; n < NREG; n++) s += sh_sc[n] * fp[n * EE];
                g_ctx[b * EE + e] = s;
            }
        }
        gridbar();

        for (int task = wid_g; task < BB * EE; task += nwarps) {
            int b = task >> 9, eo = task & 511;
            int tok = captions[b * SEQ + t];
            const float* wr = rW + (size_t)eo * (EE + HH);
            float s = warpdot512(wr, g_ctx + b * EE, lane);
            const float* ew = embed_W + (size_t)tok * EE;
            float s2 = 0.f;
#pragma unroll
            for (int c = 0; c < 4; c++) {
                float4 av = *(const float4*)(wr + 512 + c * 128 + lane * 4);
                float4 bv = *(const float4*)(ew + c * 128 + lane * 4);
                s2 += av.x * bv.x + av.y * bv.y + av.z * bv.z + av.w * bv.w;
            }
            s += s2 * 22.62741699796952f;
            s = warpsum(s);
            if (lane == 0) g_x[task] = s + rb[eo];
        }
        gridbar();

        for (int task = wid_g; task < BB * HH; task += nwarps) {
            int b = task >> 9, hi = task & 511;
            const float* xb = g_x + b * EE;
            const float* hb = hcur + b * HH;
            float acc[4];
#pragma unroll
            for (int gi = 0; gi < 4; gi++) {
                int j = gi * HH + hi;
                float s = warpdot512(Wih + (size_t)j * EE, xb, lane)
                        + warpdot512(Whh + (size_t)j * HH, hb, lane);
                acc[gi] = warpsum(s);
            }
            if (lane == 0) {
                float iv = acc[0] + bih[hi]          + bhh[hi];
                float fv = acc[1] + bih[HH + hi]     + bhh[HH + hi];
                float gv = acc[2] + bih[2 * HH + hi] + bhh[2 * HH + hi];
                float ov = acc[3] + bih[3 * HH + hi] + bhh[3 * HH + hi];
                float si = 1.f / (1.f + __expf(-iv));
                float sf = 1.f / (1.f + __expf(-fv));
                float so = 1.f / (1.f + __expf(-ov));
                float c2 = sf * g_c[task] + si * tanhf(gv);
                float h2 = so * tanhf(c2);
                g_c[task] = c2;
                hnxt[task] = h2;
                g_Hall[((size_t)t * BB + b) * HH + hi] = h2;
            }
        }
        gridbar();
    }
}

// ---------------- fp32 -> bf16 hi/lo split ----------------
__device__ __forceinline__ void split_store(float4 v, __nv_bfloat16* H,
                                            __nv_bfloat16* L, size_t off) {
    __nv_bfloat162 h0, h1, l0, l1;
    h0.x = __float2bfloat16(v.x); h0.y = __float2bfloat16(v.y);
    h1.x = __float2bfloat16(v.z); h1.y = __float2bfloat16(v.w);
    l0.x = __float2bfloat16(v.x - __bfloat162float(h0.x));
    l0.y = __float2bfloat16(v.y - __bfloat162float(h0.y));
    l1.x = __float2bfloat16(v.z - __bfloat162float(h1.x));
    l1.y = __float2bfloat16(v.w - __bfloat162float(h1.y));
    *(__nv_bfloat162*)(H + off) = h0; *(__nv_bfloat162*)(H + off + 2) = h1;
    *(__nv_bfloat162*)(L + off) = l0; *(__nv_bfloat162*)(L + off + 2) = l1;
}

__global__ void __launch_bounds__(256) convert_kernel(const float* __restrict__ outW)
{
    const size_t NW4 = ((size_t)VV * EE) / 4;
    const size_t NA4 = ((size_t)SEQ * BB * HH) / 4;
    size_t stride = (size_t)gridDim.x * blockDim.x;
    for (size_t i = (size_t)blockIdx.x * blockDim.x + threadIdx.x;
         i < NW4 + NA4; i += stride) {
        if (i < NW4) {
            float4 v = ((const float4*)outW)[i];
            split_store(v, g_WH, g_WL, i * 4);
        } else {
            size_t j = i - NW4;
            float4 v = ((const float4*)g_Hall)[j];
            split_store(v, g_AH, g_AL, j * 4);
        }
    }
}

// ---------------- tensor-core output GEMM ----------------
// out[m=t*32+b][n] = Hall[m] . outW[n] + outb[n],  bf16 hi/lo split, 3 mma passes
#define LDSW 40  // padded smem row stride (bf16 elems); 80B rows -> conflict-free ldmatrix

__device__ __forceinline__ uint32_t s2u(const void* p) {
    return (uint32_t)__cvta_generic_to_shared(p);
}
__device__ __forceinline__ void ldsm_x4(uint32_t r[4], uint32_t addr) {
    asm volatile("ldmatrix.sync.aligned.m8n8.x4.shared.b16 {%0,%1,%2,%3}, [%4];"
                 : "=r"(r[0]), "=r"(r[1]), "=r"(r[2]), "=r"(r[3]) : "r"(addr));
}
__device__ __forceinline__ void mma_bf16(float c[4], const uint32_t a[4], const uint32_t b[2]) {
    asm volatile("mma.sync.aligned.m16n8k16.row.col.f32.bf16.bf16.f32 "
                 "{%0,%1,%2,%3}, {%4,%5,%6,%7}, {%8,%9}, {%0,%1,%2,%3};"
                 : "+f"(c[0]), "+f"(c[1]), "+f"(c[2]), "+f"(c[3])
                 : "r"(a[0]), "r"(a[1]), "r"(a[2]), "r"(a[3]), "r"(b[0]), "r"(b[1]));
}

__global__ void __launch_bounds__(256) out_gemm_tc(
    const float* __restrict__ outb, float* __restrict__ out)
{
    __shared__ __align__(16) __nv_bfloat16 sAH[128 * LDSW];
    __shared__ __align__(16) __nv_bfloat16 sAL[128 * LDSW];
    __shared__ __align__(16) __nv_bfloat16 sBH[128 * LDSW];
    __shared__ __align__(16) __nv_bfloat16 sBL[128 * LDSW];

    const int tid  = threadIdx.x;
    const int lane = tid & 31;
    const int w    = tid >> 5;
    const int wm   = w >> 2;        // 0..1
    const int wn   = w & 3;         // 0..3
    const int m0 = blockIdx.y * 128;
    const int n0 = blockIdx.x * 128;

    float acc[4][4][4];
#pragma unroll
    for (int mt = 0; mt < 4; mt++)
#pragma unroll
        for (int nt = 0; nt < 4; nt++)
#pragma unroll
            for (int r = 0; r < 4; r++) acc[mt][nt][r] = 0.f;

    // ldmatrix lane-address components (element units)
    const int a_row = lane & 15;
    const int a_k8  = (lane >> 4) * 8;
    const int b_nrw = (lane & 7) + ((lane >> 4) << 3);
    const int b_k8  = ((lane >> 3) & 1) * 8;

    const uint32_t uAH = s2u(sAH), uAL = s2u(sAL);
    const uint32_t uBH = s2u(sBH), uBL = s2u(sBL);

    for (int k0 = 0; k0 < 512; k0 += 32) {
        __syncthreads();
#pragma unroll
        for (int i = 0; i < 2; i++) {
            int v = tid + i * 256;          // 0..511 vec8 slots
            int row = v >> 2;
            int kc  = (v & 3) * 8;
            size_t ga = (size_t)(m0 + row) * 512 + k0 + kc;
            size_t gb = (size_t)(n0 + row) * 512 + k0 + kc;
            int so = row * LDSW + kc;
            *(uint4*)(sAH + so) = *(const uint4*)(g_AH + ga);
            *(uint4*)(sAL + so) = *(const uint4*)(g_AL + ga);
            *(uint4*)(sBH + so) = *(const uint4*)(g_WH + gb);
            *(uint4*)(sBL + so) = *(const uint4*)(g_WL + gb);
        }
        __syncthreads();

#pragma unroll
        for (int ks = 0; ks < 32; ks += 16) {
            uint32_t aH[4][4], aL[4][4];
#pragma unroll
            for (int mt = 0; mt < 4; mt++) {
                int off = ((wm * 64 + mt * 16 + a_row) * LDSW + ks + a_k8) * 2;
                ldsm_x4(aH[mt], uAH + off);
                ldsm_x4(aL[mt], uAL + off);
            }
            uint32_t bH[4][2], bL[4][2];
#pragma unroll
            for (int p = 0; p < 2; p++) {
                int off = ((wn * 32 + p * 16 + b_nrw) * LDSW + ks + b_k8) * 2;
                uint32_t r[4];
                ldsm_x4(r, uBH + off);
                bH[2 * p][0] = r[0]; bH[2 * p][1] = r[1];
                bH[2 * p + 1][0] = r[2]; bH[2 * p + 1][1] = r[3];
                ldsm_x4(r, uBL + off);
                bL[2 * p][0] = r[0]; bL[2 * p][1] = r[1];
                bL[2 * p + 1][0] = r[2]; bL[2 * p + 1][1] = r[3];
            }
#pragma unroll
            for (int mt = 0; mt < 4; mt++)
#pragma unroll
                for (int nt = 0; nt < 4; nt++) {
                    mma_bf16(acc[mt][nt], aH[mt], bH[nt]);
                    mma_bf16(acc[mt][nt], aH[mt], bL[nt]);
                    mma_bf16(acc[mt][nt], aL[mt], bH[nt]);
                }
        }
    }

    // epilogue: m = t*32 + b  ->  out[b][t][:]
#pragma unroll
    for (int mt = 0; mt < 4; mt++) {
#pragma unroll
        for (int half = 0; half < 2; half++) {
            int m = m0 + wm * 64 + mt * 16 + (lane >> 2) + half * 8;
            int tt = m >> 5, b = m & 31;
            float* orow = out + ((size_t)b * SEQ + tt) * VV;
#pragma unroll
            for (int nt = 0; nt < 4; nt++) {
                int n = n0 + wn * 32 + nt * 8 + 2 * (lane & 3);
                float2 bias = *(const float2*)(outb + n);
                float2 v;
                v.x = acc[mt][nt][2 * half + 0] + bias.x;
                v.y = acc[mt][nt][2 * half + 1] + bias.y;
                *(float2*)(orow + n) = v;
            }
        }
    }
}

extern "C" void kernel_launch(void* const* d_in, const int* in_sizes, int n_in,
                              void* d_out, int out_size)
{
    const float* features = (const float*)d_in[0];
    const int*   captions = (const int*)d_in[1];
    const float* embed_W  = (const float*)d_in[2];
    const float* ihW = (const float*)d_in[3];
    const float* ihb = (const float*)d_in[4];
    const float* icW = (const float*)d_in[5];
    const float* icb = (const float*)d_in[6];
    const float* rW  = (const float*)d_in[7];
    const float* rb  = (const float*)d_in[8];
    const float* Wih = (const float*)d_in[9];
    const float* Whh = (const float*)d_in[10];
    const float* bih = (const float*)d_in[11];
    const float* bhh = (const float*)d_in[12];
    const float* outW = (const float*)d_in[13];
    const float* outb = (const float*)d_in[14];

    recurrence_kernel<<<NBLK, NTHR>>>(features, captions, embed_W,
                                      ihW, ihb, icW, icb, rW, rb,
                                      Wih, Whh, bih, bhh);
    convert_kernel<<<2048, 256>>>(outW);
    dim3 grid(VV / 128, (SEQ * BB) / 128);
    out_gemm_tc<<<grid, 256>>>(outb, (float*)d_out);
}

// round 7
// speedup vs baseline: 1.7634x; 1.0917x over previous
#include <cuda_runtime.h>
#include <cuda_bf16.h>
#include <math.h>
#include <stdint.h>

#define BB 32
#define NREG 196
#define EE 512
#define HH 512
#define SEQ 64
#define VV 32000

#define NBLK 148
#define NTHR 256

// ---------------- scratch (device globals; no allocations) ----------------
__device__ float g_fmean[BB * EE];
__device__ float g_hbuf[2][BB * HH];        // [b][k]   (attention)
__device__ float g_hT[2][HH * BB];          // [k][b]   (gate GEMM)
__device__ float g_cT[HH * BB];             // [k][b]
__device__ float g_sc[BB * NREG];
__device__ float g_actCE[2 * EE * BB];      // [k][b]: k<512 ctx, k>=512 emb*sqrtE
__device__ float g_actX[EE * BB];           // [k][b]: x
__device__ __align__(16) float g_Hall[SEQ * BB * HH];   // row (t*32+b)
__device__ unsigned g_bar_count;
__device__ unsigned g_bar_gen;

// bf16 split buffers for tensor-core GEMM
__device__ __align__(16) __nv_bfloat16 g_AH[SEQ * BB * HH];
__device__ __align__(16) __nv_bfloat16 g_AL[SEQ * BB * HH];
__device__ __align__(16) __nv_bfloat16 g_WH[(size_t)VV * EE];
__device__ __align__(16) __nv_bfloat16 g_WL[(size_t)VV * EE];

// ---------------- grid-wide barrier ----------------
__device__ __forceinline__ void gridbar() {
    __syncthreads();
    if (threadIdx.x == 0) {
        unsigned gen = *((volatile unsigned*)&g_bar_gen);
        __threadfence();
        if (atomicAdd(&g_bar_count, 1u) == (unsigned)(gridDim.x - 1)) {
            g_bar_count = 0;
            __threadfence();
            atomicAdd(&g_bar_gen, 1u);
        } else {
            while (*((volatile unsigned*)&g_bar_gen) == gen) { __nanosleep(32); }
        }
        __threadfence();
    }
    __syncthreads();
}

__device__ __forceinline__ float warpsum(float v) {
#pragma unroll
    for (int o = 16; o; o >>= 1) v += __shfl_xor_sync(0xffffffffu, v, o);
    return v;
}

__device__ __forceinline__ float warpdot512(const float* __restrict__ a,
                                            const float* __restrict__ b, int lane) {
    float s = 0.f;
#pragma unroll
    for (int c = 0; c < 4; c++) {
        float4 av = *(const float4*)(a + c * 128 + lane * 4);
        float4 bv = *(const float4*)(b + c * 128 + lane * 4);
        s += av.x * bv.x + av.y * bv.y + av.z * bv.z + av.w * bv.w;
    }
    return s;
}

// ---------------- persistent recurrence kernel ----------------
__global__ void __launch_bounds__(NTHR) recurrence_kernel(
    const float* __restrict__ features, const int* __restrict__ captions,
    const float* __restrict__ embed_W,
    const float* __restrict__ ihW, const float* __restrict__ ihb,
    const float* __restrict__ icW, const float* __restrict__ icb,
    const float* __restrict__ rW,  const float* __restrict__ rb,
    const float* __restrict__ Wih, const float* __restrict__ Whh,
    const float* __restrict__ bih, const float* __restrict__ bhh)
{
    const int tid  = threadIdx.x;
    const int lane = tid & 31;
    const int w    = tid >> 5;
    const int gtid = blockIdx.x * NTHR + tid;
    const int wid_g  = gtid >> 5;
    const int nwarps = (NBLK * NTHR) >> 5;
    const int gstride = NBLK * NTHR;

    __shared__ __align__(16) float sh_h[EE];       // 2 KB
    __shared__ float sh_attn[NREG];
    __shared__ float sh_red[NTHR / 32];
    __shared__ __align__(16) float sAct[128 * BB]; // 16 KB
    __shared__ __align__(16) float sW[16 * 128];   // 8 KB
    __shared__ float sOut[16 * BB];                // 2 KB

    // ---- init a: fmean
    for (int idx = gtid; idx < BB * EE; idx += gstride) {
        int b = idx >> 9, e = idx & 511;
        const float* fp = features + (size_t)b * NREG * EE + e;
        float s = 0.f;
        for (int n = 0; n < NREG; n++) s += fp[n * EE];
        g_fmean[idx] = s * (1.0f / NREG);
    }
    gridbar();

    // ---- init b: h0 / c0 (warp per output)
    for (int task = wid_g; task < 2 * BB * HH; task += nwarps) {
        int which = task & 1;
        int m = task >> 1;
        int b = m >> 9, eo = m & 511;
        const float* Wrow = (which ? icW : ihW) + (size_t)eo * EE;
        float s = warpsum(warpdot512(Wrow, g_fmean + b * EE, lane));
        if (lane == 0) {
            if (which) {
                g_cT[eo * BB + b] = s + icb[eo];
            } else {
                float hv = s + ihb[eo];
                g_hbuf[0][m] = hv;
                g_hT[0][eo * BB + b] = hv;
            }
        }
    }
    gridbar();

    for (int t = 0; t < SEQ; t++) {
        const float* h_cur  = g_hbuf[t & 1];
        const float* hT_cur = g_hT[t & 1];
        float*       h_nxt  = g_hbuf[(t & 1) ^ 1];
        float*       hT_nxt = g_hT[(t & 1) ^ 1];

        // ==== P1: attention scores (128 blocks: b x n-quarter) + emb fill (20 blocks)
        if (blockIdx.x < 128) {
            int b = blockIdx.x >> 2;
            int q = blockIdx.x & 3;
            for (int e = tid; e < EE; e += NTHR) sh_h[e] = h_cur[b * EE + e];
            __syncthreads();
            int nend = q * 49 + 49;
            for (int n = q * 49 + w; n < nend; n += NTHR / 32) {
                float s = warpsum(warpdot512(features + ((size_t)b * NREG + n) * EE,
                                             sh_h, lane));
                if (lane == 0) g_sc[b * NREG + n] = s;
            }
        } else {
            int base = (blockIdx.x - 128) * NTHR + tid;
            for (int idx = base; idx < BB * EE; idx += 20 * NTHR) {
                int b = idx >> 9, k = idx & 511;
                int tok = captions[b * SEQ + t];
                g_actCE[(EE + k) * BB + b] =
                    embed_W[(size_t)tok * EE + k] * 22.62741699796952f; // sqrt(512)
            }
        }
        gridbar();

        // ==== P2: softmax (redundant per block) + context chunk (128 blocks)
        if (blockIdx.x < 128) {
            int b = blockIdx.x >> 2;
            int chunk = blockIdx.x & 3;

            float v = (tid < NREG) ? g_sc[b * NREG + tid] : -1e30f;
            float m = v;
#pragma unroll
            for (int o = 16; o; o >>= 1) m = fmaxf(m, __shfl_xor_sync(0xffffffffu, m, o));
            if (lane == 0) sh_red[w] = m;
            __syncthreads();
            float mx = sh_red[0];
#pragma unroll
            for (int i = 1; i < NTHR / 32; i++) mx = fmaxf(mx, sh_red[i]);

            float ev = (tid < NREG) ? __expf(v - mx) : 0.f;
            float ps = warpsum(ev);
            __syncthreads();
            if (lane == 0) sh_red[w] = ps;
            __syncthreads();
            float tot = 0.f;
#pragma unroll
            for (int i = 0; i < NTHR / 32; i++) tot += sh_red[i];
            if (tid < NREG) sh_attn[tid] = ev / tot;
            __syncthreads();

            if (tid < 128) {
                int e = chunk * 128 + tid;
                const float* fp = features + (size_t)b * NREG * EE + e;
                float s = 0.f;
#pragma unroll 8
                for (int n = 0; n < NREG; n++) s += sh_attn[n] * fp[n * EE];
                g_actCE[e * BB + b] = s;
            }
        }
        gridbar();

        // ==== P3: x = rW @ [ctx; emb] + rb   (64 blocks x 8 rows, lane = batch)
        if (blockIdx.x < 64) {
            int r0 = blockIdx.x * 8;
            float acc = 0.f;
            for (int kc = 0; kc < 8; kc++) {
                __syncthreads();
                const float* asrc = g_actCE + kc * 128 * BB;
                for (int i = tid; i < 128 * BB; i += NTHR) sAct[i] = asrc[i];
                for (int i = tid; i < 8 * 128; i += NTHR) {
                    int r = i >> 7, k = i & 127;
                    sW[i] = rW[(size_t)(r0 + r) * (EE + HH) + kc * 128 + k];
                }
                __syncthreads();
                const float* wp = sW + w * 128;
#pragma unroll
                for (int k = 0; k < 128; k += 4) {
                    float4 wv = *(const float4*)(wp + k);
                    acc += wv.x * sAct[(k + 0) * BB + lane];
                    acc += wv.y * sAct[(k + 1) * BB + lane];
                    acc += wv.z * sAct[(k + 2) * BB + lane];
                    acc += wv.w * sAct[(k + 3) * BB + lane];
                }
            }
            g_actX[(r0 + w) * BB + lane] = acc + rb[r0 + w];
        }
        gridbar();

        // ==== P4: gates + cell. 128 blocks x 16 row' (row' = hi*4 + gate), lane = b
        if (blockIdx.x < 128) {
            int rp0 = blockIdx.x * 16;
            int r0l = w * 2, r1l = w * 2 + 1;
            float acc0 = 0.f, acc1 = 0.f;
            for (int kc = 0; kc < 8; kc++) {
                __syncthreads();
                const float* asrc = (kc < 4) ? (g_actX + kc * 128 * BB)
                                             : (hT_cur + (kc - 4) * 128 * BB);
                for (int i = tid; i < 128 * BB; i += NTHR) sAct[i] = asrc[i];
                for (int i = tid; i < 16 * 128; i += NTHR) {
                    int rl = i >> 7, k = i & 127;
                    int rp = rp0 + rl;
                    int hi = rp >> 2, gate = rp & 3;
                    sW[i] = (kc < 4)
                        ? Wih[(size_t)(gate * HH + hi) * EE + kc * 128 + k]
                        : Whh[(size_t)(gate * HH + hi) * HH + (kc - 4) * 128 + k];
                }
                __syncthreads();
                const float* w0p = sW + r0l * 128;
                const float* w1p = sW + r1l * 128;
#pragma unroll
                for (int k = 0; k < 128; k += 4) {
                    float4 w0 = *(const float4*)(w0p + k);
                    float4 w1 = *(const float4*)(w1p + k);
                    float a0 = sAct[(k + 0) * BB + lane];
                    float a1 = sAct[(k + 1) * BB + lane];
                    float a2 = sAct[(k + 2) * BB + lane];
                    float a3 = sAct[(k + 3) * BB + lane];
                    acc0 += w0.x * a0 + w0.y * a1 + w0.z * a2 + w0.w * a3;
                    acc1 += w1.x * a0 + w1.y * a1 + w1.z * a2 + w1.w * a3;
                }
            }
            sOut[r0l * BB + lane] = acc0;
            sOut[r1l * BB + lane] = acc1;
            __syncthreads();
            if (tid < 128) {
                int hl = tid >> 5;
                int b  = lane;
                int hi = (rp0 >> 2) + hl;
                float iv = sOut[(hl * 4 + 0) * BB + b] + bih[hi]          + bhh[hi];
                float fv = sOut[(hl * 4 + 1) * BB + b] + bih[HH + hi]     + bhh[HH + hi];
                float gv = sOut[(hl * 4 + 2) * BB + b] + bih[2 * HH + hi] + bhh[2 * HH + hi];
                float ov = sOut[(hl * 4 + 3) * BB + b] + bih[3 * HH + hi] + bhh[3 * HH + hi];
                float si = 1.f / (1.f + __expf(-iv));
                float sf = 1.f / (1.f + __expf(-fv));
                float so = 1.f / (1.f + __expf(-ov));
                float c2 = sf * g_cT[hi * BB + b] + si * tanhf(gv);
                float h2 = so * tanhf(c2);
                g_cT[hi * BB + b] = c2;
                hT_nxt[hi * BB + b] = h2;
                h_nxt[b * HH + hi] = h2;
                g_Hall[((size_t)t * BB + b) * HH + hi] = h2;
            }
        }
        gridbar();
    }
}

// ---------------- fp32 -> bf16 hi/lo split ----------------
__device__ __forceinline__ void split_store(float4 v, __nv_bfloat16* H,
                                            __nv_bfloat16* L, size_t off) {
    __nv_bfloat162 h0, h1, l0, l1;
    h0.x = __float2bfloat16(v.x); h0.y = __float2bfloat16(v.y);
    h1.x = __float2bfloat16(v.z); h1.y = __float2bfloat16(v.w);
    l0.x = __float2bfloat16(v.x - __bfloat162float(h0.x));
    l0.y = __float2bfloat16(v.y - __bfloat162float(h0.y));
    l1.x = __float2bfloat16(v.z - __bfloat162float(h1.x));
    l1.y = __float2bfloat16(v.w - __bfloat162float(h1.y));
    *(__nv_bfloat162*)(H + off) = h0; *(__nv_bfloat162*)(H + off + 2) = h1;
    *(__nv_bfloat162*)(L + off) = l0; *(__nv_bfloat162*)(L + off + 2) = l1;
}

__global__ void __launch_bounds__(256) convert_kernel(const float* __restrict__ outW)
{
    const size_t NW4 = ((size_t)VV * EE) / 4;
    const size_t NA4 = ((size_t)SEQ * BB * HH) / 4;
    size_t stride = (size_t)gridDim.x * blockDim.x;
    for (size_t i = (size_t)blockIdx.x * blockDim.x + threadIdx.x;
         i < NW4 + NA4; i += stride) {
        if (i < NW4) {
            float4 v = ((const float4*)outW)[i];
            split_store(v, g_WH, g_WL, i * 4);
        } else {
            size_t j = i - NW4;
            float4 v = ((const float4*)g_Hall)[j];
            split_store(v, g_AH, g_AL, j * 4);
        }
    }
}

// ---------------- tensor-core output GEMM ----------------
#define LDSW 40  // padded smem row stride (bf16 elems)

__device__ __forceinline__ uint32_t s2u(const void* p) {
    return (uint32_t)__cvta_generic_to_shared(p);
}
__device__ __forceinline__ void ldsm_x4(uint32_t r[4], uint32_t addr) {
    asm volatile("ldmatrix.sync.aligned.m8n8.x4.shared.b16 {%0,%1,%2,%3}, [%4];"
                 : "=r"(r[0]), "=r"(r[1]), "=r"(r[2]), "=r"(r[3]) : "r"(addr));
}
__device__ __forceinline__ void mma_bf16(float c[4], const uint32_t a[4], const uint32_t b[2]) {
    asm volatile("mma.sync.aligned.m16n8k16.row.col.f32.bf16.bf16.f32 "
                 "{%0,%1,%2,%3}, {%4,%5,%6,%7}, {%8,%9}, {%0,%1,%2,%3};"
                 : "+f"(c[0]), "+f"(c[1]), "+f"(c[2]), "+f"(c[3])
                 : "r"(a[0]), "r"(a[1]), "r"(a[2]), "r"(a[3]), "r"(b[0]), "r"(b[1]));
}

__global__ void __launch_bounds__(256) out_gemm_tc(
    const float* __restrict__ outb, float* __restrict__ out)
{
    __shared__ __align__(16) __nv_bfloat16 sAH[128 * LDSW];
    __shared__ __align__(16) __nv_bfloat16 sAL[128 * LDSW];
    __shared__ __align__(16) __nv_bfloat16 sBH[128 * LDSW];
    __shared__ __align__(16) __nv_bfloat16 sBL[128 * LDSW];

    const int tid  = threadIdx.x;
    const int lane = tid & 31;
    const int w    = tid >> 5;
    const int wm   = w >> 2;
    const int wn   = w & 3;
    const int m0 = blockIdx.y * 128;
    const int n0 = blockIdx.x * 128;

    float acc[4][4][4];
#pragma unroll
    for (int mt = 0; mt < 4; mt++)
#pragma unroll
        for (int nt = 0; nt < 4; nt++)
#pragma unroll
            for (int r = 0; r < 4; r++) acc[mt][nt][r] = 0.f;

    const int a_row = lane & 15;
    const int a_k8  = (lane >> 4) * 8;
    const int b_nrw = (lane & 7) + ((lane >> 4) << 3);
    const int b_k8  = ((lane >> 3) & 1) * 8;

    const uint32_t uAH = s2u(sAH), uAL = s2u(sAL);
    const uint32_t uBH = s2u(sBH), uBL = s2u(sBL);

    for (int k0 = 0; k0 < 512; k0 += 32) {
        __syncthreads();
#pragma unroll
        for (int i = 0; i < 2; i++) {
            int v = tid + i * 256;
            int row = v >> 2;
            int kc  = (v & 3) * 8;
            size_t ga = (size_t)(m0 + row) * 512 + k0 + kc;
            size_t gb = (size_t)(n0 + row) * 512 + k0 + kc;
            int so = row * LDSW + kc;
            *(uint4*)(sAH + so) = *(const uint4*)(g_AH + ga);
            *(uint4*)(sAL + so) = *(const uint4*)(g_AL + ga);
            *(uint4*)(sBH + so) = *(const uint4*)(g_WH + gb);
            *(uint4*)(sBL + so) = *(const uint4*)(g_WL + gb);
        }
        __syncthreads();

#pragma unroll
        for (int ks = 0; ks < 32; ks += 16) {
            uint32_t aH[4][4], aL[4][4];
#pragma unroll
            for (int mt = 0; mt < 4; mt++) {
                int off = ((wm * 64 + mt * 16 + a_row) * LDSW + ks + a_k8) * 2;
                ldsm_x4(aH[mt], uAH + off);
                ldsm_x4(aL[mt], uAL + off);
            }
            uint32_t bH[4][2], bL[4][2];
#pragma unroll
            for (int p = 0; p < 2; p++) {
                int off = ((wn * 32 + p * 16 + b_nrw) * LDSW + ks + b_k8) * 2;
                uint32_t r[4];
                ldsm_x4(r, uBH + off);
                bH[2 * p][0] = r[0]; bH[2 * p][1] = r[1];
                bH[2 * p + 1][0] = r[2]; bH[2 * p + 1][1] = r[3];
                ldsm_x4(r, uBL + off);
                bL[2 * p][0] = r[0]; bL[2 * p][1] = r[1];
                bL[2 * p + 1][0] = r[2]; bL[2 * p + 1][1] = r[3];
            }
#pragma unroll
            for (int mt = 0; mt < 4; mt++)
#pragma unroll
                for (int nt = 0; nt < 4; nt++) {
                    mma_bf16(acc[mt][nt], aH[mt], bH[nt]);
                    mma_bf16(acc[mt][nt], aH[mt], bL[nt]);
                    mma_bf16(acc[mt][nt], aL[mt], bH[nt]);
                }
        }
    }

#pragma unroll
    for (int mt = 0; mt < 4; mt++) {
#pragma unroll
        for (int half = 0; half < 2; half++) {
            int m = m0 + wm * 64 + mt * 16 + (lane >> 2) + half * 8;
            int tt = m >> 5, b = m & 31;
            float* orow = out + ((size_t)b * SEQ + tt) * VV;
#pragma unroll
            for (int nt = 0; nt < 4; nt++) {
                int n = n0 + wn * 32 + nt * 8 + 2 * (lane & 3);
                float2 bias = *(const float2*)(outb + n);
                float2 v;
                v.x = acc[mt][nt][2 * half + 0] + bias.x;
                v.y = acc[mt][nt][2 * half + 1] + bias.y;
                *(float2*)(orow + n) = v;
            }
        }
    }
}

extern "C" void kernel_launch(void* const* d_in, const int* in_sizes, int n_in,
                              void* d_out, int out_size)
{
    const float* features = (const float*)d_in[0];
    const int*   captions = (const int*)d_in[1];
    const float* embed_W  = (const float*)d_in[2];
    const float* ihW = (const float*)d_in[3];
    const float* ihb = (const float*)d_in[4];
    const float* icW = (const float*)d_in[5];
    const float* icb = (const float*)d_in[6];
    const float* rW  = (const float*)d_in[7];
    const float* rb  = (const float*)d_in[8];
    const float* Wih = (const float*)d_in[9];
    const float* Whh = (const float*)d_in[10];
    const float* bih = (const float*)d_in[11];
    const float* bhh = (const float*)d_in[12];
    const float* outW = (const float*)d_in[13];
    const float* outb = (const float*)d_in[14];

    recurrence_kernel<<<NBLK, NTHR>>>(features, captions, embed_W,
                                      ihW, ihb, icW, icb, rW, rb,
                                      Wih, Whh, bih, bhh);
    convert_kernel<<<2048, 256>>>(outW);
    dim3 grid(VV / 128, (SEQ * BB) / 128);
    out_gemm_tc<<<grid, 256>>>(outb, (float*)d_out);
}

// round 8
// speedup vs baseline: 2.4403x; 1.3838x over previous
#include <cuda_runtime.h>
#include <cuda_bf16.h>
#include <math.h>
#include <stdint.h>

#define BB 32
#define NREG 196
#define EE 512
#define HH 512
#define SEQ 64
#define VV 32000

#define NBLK 148
#define NTHR 512

// ---------------- scratch (device globals; no allocations) ----------------
__device__ float g_fmean[BB * EE];
__device__ __align__(16) float g_hbuf[2][BB * HH];   // [b][k]   (attention)
__device__ __align__(16) float g_hT[2][HH * BB];     // [k][b]   (gate GEMM)
__device__ float g_cT[HH * BB];                      // [k][b]
__device__ __align__(16) float g_actCE[2 * EE * BB]; // [k][b]: k<512 ctx, k>=512 emb*sqrtE
__device__ __align__(16) float g_actX[EE * BB];      // [k][b]: x
__device__ __align__(16) float g_Hall[SEQ * BB * HH];// row (t*32+b)
__device__ unsigned g_bar_count;
__device__ unsigned g_bar_gen;

// bf16 split buffers for tensor-core GEMM
__device__ __align__(16) __nv_bfloat16 g_AH[SEQ * BB * HH];
__device__ __align__(16) __nv_bfloat16 g_AL[SEQ * BB * HH];
__device__ __align__(16) __nv_bfloat16 g_WH[(size_t)VV * EE];
__device__ __align__(16) __nv_bfloat16 g_WL[(size_t)VV * EE];

// ---------------- grid-wide barrier ----------------
__device__ __forceinline__ void gridbar() {
    __syncthreads();
    if (threadIdx.x == 0) {
        unsigned gen = *((volatile unsigned*)&g_bar_gen);
        __threadfence();
        if (atomicAdd(&g_bar_count, 1u) == (unsigned)(gridDim.x - 1)) {
            g_bar_count = 0;
            __threadfence();
            atomicAdd(&g_bar_gen, 1u);
        } else {
            while (*((volatile unsigned*)&g_bar_gen) == gen) { __nanosleep(32); }
        }
        __threadfence();
    }
    __syncthreads();
}

__device__ __forceinline__ float warpsum(float v) {
#pragma unroll
    for (int o = 16; o; o >>= 1) v += __shfl_xor_sync(0xffffffffu, v, o);
    return v;
}

__device__ __forceinline__ float warpdot512(const float* __restrict__ a,
                                            const float* __restrict__ b, int lane) {
    float s = 0.f;
#pragma unroll
    for (int c = 0; c < 4; c++) {
        float4 av = *(const float4*)(a + c * 128 + lane * 4);
        float4 bv = *(const float4*)(b + c * 128 + lane * 4);
        s += av.x * bv.x + av.y * bv.y + av.z * bv.z + av.w * bv.w;
    }
    return s;
}

// ---------------- persistent recurrence kernel ----------------
__global__ void __launch_bounds__(NTHR) recurrence_kernel(
    const float* __restrict__ features, const int* __restrict__ captions,
    const float* __restrict__ embed_W,
    const float* __restrict__ ihW, const float* __restrict__ ihb,
    const float* __restrict__ icW, const float* __restrict__ icb,
    const float* __restrict__ rW,  const float* __restrict__ rb,
    const float* __restrict__ Wih, const float* __restrict__ Whh,
    const float* __restrict__ bih, const float* __restrict__ bhh)
{
    const int tid  = threadIdx.x;
    const int lane = tid & 31;
    const int w    = tid >> 5;
    const int gtid = blockIdx.x * NTHR + tid;
    const int wid_g  = gtid >> 5;
    const int nwarps = (NBLK * NTHR) >> 5;
    const int gstride = NBLK * NTHR;

    __shared__ __align__(16) float sh_h[EE];        // 2 KB
    __shared__ float sSc[NREG];
    __shared__ float sh_attn[NREG];
    __shared__ float sh_red[NTHR / 32];
    __shared__ __align__(16) float sPart[16 * 128]; // 8 KB
    __shared__ __align__(16) float sAct[128 * BB];  // 16 KB
    __shared__ __align__(16) float sW[16 * 128];    // 8 KB
    __shared__ float sOut[16 * BB];                 // 2 KB

    // ---- init a: fmean
    for (int idx = gtid; idx < BB * EE; idx += gstride) {
        int b = idx >> 9, e = idx & 511;
        const float* fp = features + (size_t)b * NREG * EE + e;
        float s = 0.f;
        for (int n = 0; n < NREG; n++) s += fp[n * EE];
        g_fmean[idx] = s * (1.0f / NREG);
    }
    gridbar();

    // ---- init b: h0 / c0 (warp per output)
    for (int task = wid_g; task < 2 * BB * HH; task += nwarps) {
        int which = task & 1;
        int m = task >> 1;
        int b = m >> 9, eo = m & 511;
        const float* Wrow = (which ? icW : ihW) + (size_t)eo * EE;
        float s = warpsum(warpdot512(Wrow, g_fmean + b * EE, lane));
        if (lane == 0) {
            if (which) {
                g_cT[eo * BB + b] = s + icb[eo];
            } else {
                float hv = s + ihb[eo];
                g_hbuf[0][m] = hv;
                g_hT[0][eo * BB + b] = hv;
            }
        }
    }
    gridbar();

    for (int t = 0; t < SEQ; t++) {
        const float* h_cur  = g_hbuf[t & 1];
        const float* hT_cur = g_hT[t & 1];
        float*       h_nxt  = g_hbuf[(t & 1) ^ 1];
        float*       hT_nxt = g_hT[(t & 1) ^ 1];

        // ==== P12: attention (scores redundant per (b,chunk) block) + emb fill
        if (blockIdx.x < 128) {
            const int b = blockIdx.x >> 2;
            const int chunk = blockIdx.x & 3;
            const float* fb = features + (size_t)b * NREG * EE;

            // stage h
            sh_h[tid] = h_cur[b * EE + tid];
            __syncthreads();

            // scores: warp-distributed n
            for (int n = w; n < NREG; n += 16) {
                float s = warpsum(warpdot512(fb + (size_t)n * EE, sh_h, lane));
                if (lane == 0) sSc[n] = s;
            }
            __syncthreads();

            // softmax over 196 (all 512 threads help reduce)
            float v = (tid < NREG) ? sSc[tid] : -1e30f;
            float m = v;
#pragma unroll
            for (int o = 16; o; o >>= 1) m = fmaxf(m, __shfl_xor_sync(0xffffffffu, m, o));
            if (lane == 0) sh_red[w] = m;
            __syncthreads();
            float mx = sh_red[0];
#pragma unroll
            for (int i = 1; i < 16; i++) mx = fmaxf(mx, sh_red[i]);
            float ev = (tid < NREG) ? __expf(v - mx) : 0.f;
            float ps = warpsum(ev);
            __syncthreads();
            if (lane == 0) sh_red[w] = ps;
            __syncthreads();
            float tot = 0.f;
#pragma unroll
            for (int i = 0; i < 16; i++) tot += sh_red[i];
            if (tid < NREG) sh_attn[tid] = ev / tot;
            __syncthreads();

            // context chunk: warp-distributed n, float4 lanes, partials in smem
            float4 cacc = make_float4(0.f, 0.f, 0.f, 0.f);
            const float* fc = fb + chunk * 128 + lane * 4;
#pragma unroll 4
            for (int n = w; n < NREG; n += 16) {
                float a = sh_attn[n];
                float4 fv = *(const float4*)(fc + (size_t)n * EE);
                cacc.x += a * fv.x; cacc.y += a * fv.y;
                cacc.z += a * fv.z; cacc.w += a * fv.w;
            }
            *(float4*)(sPart + w * 128 + lane * 4) = cacc;
            __syncthreads();
            if (tid < 128) {
                float s = 0.f;
#pragma unroll
                for (int i = 0; i < 16; i++) s += sPart[i * 128 + tid];
                g_actCE[(chunk * 128 + tid) * BB + b] = s;
            }
        } else {
            // emb fill (20 blocks)
            for (int idx = (blockIdx.x - 128) * NTHR + tid; idx < BB * EE;
                 idx += 20 * NTHR) {
                int b = idx >> 9, k = idx & 511;
                int tok = captions[b * SEQ + t];
                g_actCE[(EE + k) * BB + b] =
                    embed_W[(size_t)tok * EE + k] * 22.62741699796952f; // sqrt(512)
            }
        }
        gridbar();

        // ==== P3: x = rW @ [ctx; emb] + rb  (128 blocks x 4 rows, warp=(row,kq))
        if (blockIdx.x < 128) {
            const int r0 = blockIdx.x * 4;
            const int row = w >> 2, q = w & 3;
            float acc = 0.f;
            for (int kc = 0; kc < 8; kc++) {
                __syncthreads();
                const float* asrc = g_actCE + kc * 128 * BB;
                for (int i4 = tid; i4 < 1024; i4 += NTHR)
                    ((float4*)sAct)[i4] = ((const float4*)asrc)[i4];
                {
                    int r = tid >> 7, k = tid & 127;
                    sW[tid] = rW[(size_t)(r0 + r) * (EE + HH) + kc * 128 + k];
                }
                __syncthreads();
                const float* wp = sW + row * 128 + q * 32;
#pragma unroll
                for (int k = 0; k < 32; k += 4) {
                    float4 wv = *(const float4*)(wp + k);
                    const float* ap = sAct + (q * 32 + k) * BB + lane;
                    acc += wv.x * ap[0 * BB];
                    acc += wv.y * ap[1 * BB];
                    acc += wv.z * ap[2 * BB];
                    acc += wv.w * ap[3 * BB];
                }
            }
            sOut[(row * 4 + q) * BB + lane] = acc;
            __syncthreads();
            if (tid < 128) {
                int r = tid >> 5, b = tid & 31;
                float s = sOut[(r * 4 + 0) * BB + b] + sOut[(r * 4 + 1) * BB + b]
                        + sOut[(r * 4 + 2) * BB + b] + sOut[(r * 4 + 3) * BB + b];
                g_actX[(r0 + r) * BB + b] = s + rb[r0 + r];
            }
        }
        gridbar();

        // ==== P4: gates + cell (128 blocks x 16 rows', warp = row' = hi*4+gate)
        if (blockIdx.x < 128) {
            const int rp0 = blockIdx.x * 16;
            float acc = 0.f;
            for (int kc = 0; kc < 8; kc++) {
                __syncthreads();
                const float* asrc = (kc < 4) ? (g_actX + kc * 128 * BB)
                                             : (hT_cur + (kc - 4) * 128 * BB);
                for (int i4 = tid; i4 < 1024; i4 += NTHR)
                    ((float4*)sAct)[i4] = ((const float4*)asrc)[i4];
#pragma unroll
                for (int s = 0; s < 4; s++) {
                    int i = tid + s * NTHR;
                    int rl = i >> 7, k = i & 127;
                    int rp = rp0 + rl;
                    int hi = rp >> 2, gate = rp & 3;
                    sW[i] = (kc < 4)
                        ? Wih[(size_t)(gate * HH + hi) * EE + kc * 128 + k]
                        : Whh[(size_t)(gate * HH + hi) * HH + (kc - 4) * 128 + k];
                }
                __syncthreads();
                const float* wp = sW + w * 128;
#pragma unroll
                for (int k = 0; k < 128; k += 4) {
                    float4 wv = *(const float4*)(wp + k);
                    const float* ap = sAct + k * BB + lane;
                    acc += wv.x * ap[0 * BB];
                    acc += wv.y * ap[1 * BB];
                    acc += wv.z * ap[2 * BB];
                    acc += wv.w * ap[3 * BB];
                }
            }
            sOut[w * BB + lane] = acc;
            __syncthreads();
            if (tid < 128) {
                int hl = tid >> 5;
                int b  = tid & 31;
                int hi = blockIdx.x * 4 + hl;
                float iv = sOut[(hl * 4 + 0) * BB + b] + bih[hi]          + bhh[hi];
                float fv = sOut[(hl * 4 + 1) * BB + b] + bih[HH + hi]     + bhh[HH + hi];
                float gv = sOut[(hl * 4 + 2) * BB + b] + bih[2 * HH + hi] + bhh[2 * HH + hi];
                float ov = sOut[(hl * 4 + 3) * BB + b] + bih[3 * HH + hi] + bhh[3 * HH + hi];
                float si = 1.f / (1.f + __expf(-iv));
                float sf = 1.f / (1.f + __expf(-fv));
                float so = 1.f / (1.f + __expf(-ov));
                float c2 = sf * g_cT[hi * BB + b] + si * tanhf(gv);
                float h2 = so * tanhf(c2);
                g_cT[hi * BB + b] = c2;
                hT_nxt[hi * BB + b] = h2;
                h_nxt[b * HH + hi] = h2;
                g_Hall[((size_t)t * BB + b) * HH + hi] = h2;
            }
        }
        gridbar();
    }
}

// ---------------- fp32 -> bf16 hi/lo split ----------------
__device__ __forceinline__ void split_store(float4 v, __nv_bfloat16* H,
                                            __nv_bfloat16* L, size_t off) {
    __nv_bfloat162 h0, h1, l0, l1;
    h0.x = __float2bfloat16(v.x); h0.y = __float2bfloat16(v.y);
    h1.x = __float2bfloat16(v.z); h1.y = __float2bfloat16(v.w);
    l0.x = __float2bfloat16(v.x - __bfloat162float(h0.x));
    l0.y = __float2bfloat16(v.y - __bfloat162float(h0.y));
    l1.x = __float2bfloat16(v.z - __bfloat162float(h1.x));
    l1.y = __float2bfloat16(v.w - __bfloat162float(h1.y));
    *(__nv_bfloat162*)(H + off) = h0; *(__nv_bfloat162*)(H + off + 2) = h1;
    *(__nv_bfloat162*)(L + off) = l0; *(__nv_bfloat162*)(L + off + 2) = l1;
}

__global__ void __launch_bounds__(256) convert_kernel(const float* __restrict__ outW)
{
    const size_t NW4 = ((size_t)VV * EE) / 4;
    const size_t NA4 = ((size_t)SEQ * BB * HH) / 4;
    size_t stride = (size_t)gridDim.x * blockDim.x;
    for (size_t i = (size_t)blockIdx.x * blockDim.x + threadIdx.x;
         i < NW4 + NA4; i += stride) {
        if (i < NW4) {
            float4 v = ((const float4*)outW)[i];
            split_store(v, g_WH, g_WL, i * 4);
        } else {
            size_t j = i - NW4;
            float4 v = ((const float4*)g_Hall)[j];
            split_store(v, g_AH, g_AL, j * 4);
        }
    }
}

// ---------------- tensor-core output GEMM ----------------
#define LDSW 40  // padded smem row stride (bf16 elems)

__device__ __forceinline__ uint32_t s2u(const void* p) {
    return (uint32_t)__cvta_generic_to_shared(p);
}
__device__ __forceinline__ void ldsm_x4(uint32_t r[4], uint32_t addr) {
    asm volatile("ldmatrix.sync.aligned.m8n8.x4.shared.b16 {%0,%1,%2,%3}, [%4];"
                 : "=r"(r[0]), "=r"(r[1]), "=r"(r[2]), "=r"(r[3]) : "r"(addr));
}
__device__ __forceinline__ void mma_bf16(float c[4], const uint32_t a[4], const uint32_t b[2]) {
    asm volatile("mma.sync.aligned.m16n8k16.row.col.f32.bf16.bf16.f32 "
                 "{%0,%1,%2,%3}, {%4,%5,%6,%7}, {%8,%9}, {%0,%1,%2,%3};"
                 : "+f"(c[0]), "+f"(c[1]), "+f"(c[2]), "+f"(c[3])
                 : "r"(a[0]), "r"(a[1]), "r"(a[2]), "r"(a[3]), "r"(b[0]), "r"(b[1]));
}

__global__ void __launch_bounds__(256) out_gemm_tc(
    const float* __restrict__ outb, float* __restrict__ out)
{
    __shared__ __align__(16) __nv_bfloat16 sAH[128 * LDSW];
    __shared__ __align__(16) __nv_bfloat16 sAL[128 * LDSW];
    __shared__ __align__(16) __nv_bfloat16 sBH[128 * LDSW];
    __shared__ __align__(16) __nv_bfloat16 sBL[128 * LDSW];

    const int tid  = threadIdx.x;
    const int lane = tid & 31;
    const int w    = tid >> 5;
    const int wm   = w >> 2;
    const int wn   = w & 3;
    const int m0 = blockIdx.y * 128;
    const int n0 = blockIdx.x * 128;

    float acc[4][4][4];
#pragma unroll
    for (int mt = 0; mt < 4; mt++)
#pragma unroll
        for (int nt = 0; nt < 4; nt++)
#pragma unroll
            for (int r = 0; r < 4; r++) acc[mt][nt][r] = 0.f;

    const int a_row = lane & 15;
    const int a_k8  = (lane >> 4) * 8;
    const int b_nrw = (lane & 7) + ((lane >> 4) << 3);
    const int b_k8  = ((lane >> 3) & 1) * 8;

    const uint32_t uAH = s2u(sAH), uAL = s2u(sAL);
    const uint32_t uBH = s2u(sBH), uBL = s2u(sBL);

    for (int k0 = 0; k0 < 512; k0 += 32) {
        __syncthreads();
#pragma unroll
        for (int i = 0; i < 2; i++) {
            int v = tid + i * 256;
            int row = v >> 2;
            int kc  = (v & 3) * 8;
            size_t ga = (size_t)(m0 + row) * 512 + k0 + kc;
            size_t gb = (size_t)(n0 + row) * 512 + k0 + kc;
            int so = row * LDSW + kc;
            *(uint4*)(sAH + so) = *(const uint4*)(g_AH + ga);
            *(uint4*)(sAL + so) = *(const uint4*)(g_AL + ga);
            *(uint4*)(sBH + so) = *(const uint4*)(g_WH + gb);
            *(uint4*)(sBL + so) = *(const uint4*)(g_WL + gb);
        }
        __syncthreads();

#pragma unroll
        for (int ks = 0; ks < 32; ks += 16) {
            uint32_t aH[4][4], aL[4][4];
#pragma unroll
            for (int mt = 0; mt < 4; mt++) {
                int off = ((wm * 64 + mt * 16 + a_row) * LDSW + ks + a_k8) * 2;
                ldsm_x4(aH[mt], uAH + off);
                ldsm_x4(aL[mt], uAL + off);
            }
            uint32_t bH[4][2], bL[4][2];
#pragma unroll
            for (int p = 0; p < 2; p++) {
                int off = ((wn * 32 + p * 16 + b_nrw) * LDSW + ks + b_k8) * 2;
                uint32_t r[4];
                ldsm_x4(r, uBH + off);
                bH[2 * p][0] = r[0]; bH[2 * p][1] = r[1];
                bH[2 * p + 1][0] = r[2]; bH[2 * p + 1][1] = r[3];
                ldsm_x4(r, uBL + off);
                bL[2 * p][0] = r[0]; bL[2 * p][1] = r[1];
                bL[2 * p + 1][0] = r[2]; bL[2 * p + 1][1] = r[3];
            }
#pragma unroll
            for (int mt = 0; mt < 4; mt++)
#pragma unroll
                for (int nt = 0; nt < 4; nt++) {
                    mma_bf16(acc[mt][nt], aH[mt], bH[nt]);
                    mma_bf16(acc[mt][nt], aH[mt], bL[nt]);
                    mma_bf16(acc[mt][nt], aL[mt], bH[nt]);
                }
        }
    }

#pragma unroll
    for (int mt = 0; mt < 4; mt++) {
#pragma unroll
        for (int half = 0; half < 2; half++) {
            int m = m0 + wm * 64 + mt * 16 + (lane >> 2) + half * 8;
            int tt = m >> 5, b = m & 31;
            float* orow = out + ((size_t)b * SEQ + tt) * VV;
#pragma unroll
            for (int nt = 0; nt < 4; nt++) {
                int n = n0 + wn * 32 + nt * 8 + 2 * (lane & 3);
                float2 bias = *(const float2*)(outb + n);
                float2 v;
                v.x = acc[mt][nt][2 * half + 0] + bias.x;
                v.y = acc[mt][nt][2 * half + 1] + bias.y;
                *(float2*)(orow + n) = v;
            }
        }
    }
}

extern "C" void kernel_launch(void* const* d_in, const int* in_sizes, int n_in,
                              void* d_out, int out_size)
{
    const float* features = (const float*)d_in[0];
    const int*   captions = (const int*)d_in[1];
    const float* embed_W  = (const float*)d_in[2];
    const float* ihW = (const float*)d_in[3];
    const float* ihb = (const float*)d_in[4];
    const float* icW = (const float*)d_in[5];
    const float* icb = (const float*)d_in[6];
    const float* rW  = (const float*)d_in[7];
    const float* rb  = (const float*)d_in[8];
    const float* Wih = (const float*)d_in[9];
    const float* Whh = (const float*)d_in[10];
    const float* bih = (const float*)d_in[11];
    const float* bhh = (const float*)d_in[12];
    const float* outW = (const float*)d_in[13];
    const float* outb = (const float*)d_in[14];

    recurrence_kernel<<<NBLK, NTHR>>>(features, captions, embed_W,
                                      ihW, ihb, icW, icb, rW, rb,
                                      Wih, Whh, bih, bhh);
    convert_kernel<<<2048, 256>>>(outW);
    dim3 grid(VV / 128, (SEQ * BB) / 128);
    out_gemm_tc<<<grid, 256>>>(outb, (float*)d_out);
}